// round 16
// baseline (speedup 1.0000x reference)
#include <cuda_runtime.h>
#include <cuda_fp16.h>
#include <cstdint>
#include <math.h>

#define TE        128
#define NTHREADS  256
#define NCHUNK    56       // 1792 cols / 32 per chunk
#define NPARTS    3        // chunk-split factor per edge tile
#define NNODES    10000

#define C_A0      0.17677669529663687f   // 1/sqrt(2*16)
#define C_A0I3    0.10206207261596575f   // A0/sqrt(3)
#define C_A1      0.14433756729740643f   // 1/sqrt(3*16)
#define C_A1I2    0.10206207261596577f   // A1/sqrt(2)

// ---------------- smem byte offsets (SMEM_TOT = 110592 -> 2 CTAs/SM) ----------------
#define OFF_B     0         // 3 x (32 x 136 fp16) = 3 x 8704 = 26112
#define OFF_A     26112     // A-tile 128x136 fp16 = 34816; later v1 tile 128x52 f32 = 26624
#define OFF_MSG   60928     // 128 x 81 f32 = 41472 (phase0 overlay below)
#define OFF_EAH   60928     // ea fp16 [e][40] = 10240
#define OFF_W1H   71168     // We1 fp16 [h][40] = 10240
#define OFF_W1S   81408     // We1 f32 stage [32][129] = 16512  (ends 97920 < 102400)
#define OFF_BE2   102400    // 1792 f32 = 7168
#define OFF_BE1   109568    // 128 f32 = 512
#define OFF_DST   110080    // 128 int = 512
#define SMEM_TOT  110592

// ---------------- device scratch ----------------
__device__ float  g_acc[80 * NNODES];      // [j][n] layout
__device__ float  g_cnt[NNODES];
__device__ __half g_W2h[NCHUNK * 4352];    // per chunk: [n=32][k=136] fp16

// ---------------- helpers ----------------
__device__ __forceinline__ uint32_t smem_u32(const void* p) {
    uint32_t a;
    asm("{ .reg .u64 t; cvta.to.shared.u64 t, %1; cvt.u32.u64 %0, t; }" : "=r"(a) : "l"(p));
    return a;
}
#define CP_ASYNC16(d, s)  asm volatile("cp.async.cg.shared.global [%0], [%1], 16;" :: "r"(d), "l"(s) : "memory")
#define CP_COMMIT()       asm volatile("cp.async.commit_group;" ::: "memory")

#define LDSM_X4(r0, r1, r2, r3, addr)                                          \
    asm volatile("ldmatrix.sync.aligned.m8n8.x4.shared.b16 {%0,%1,%2,%3}, [%4];" \
        : "=r"(r0), "=r"(r1), "=r"(r2), "=r"(r3) : "r"(addr))

#define MMA16816(d, a0,a1,a2,a3, b0,b1)                                   \
    asm volatile("mma.sync.aligned.m16n8k16.row.col.f32.f16.f16.f32 "    \
        "{%0,%1,%2,%3}, {%4,%5,%6,%7}, {%8,%9}, {%0,%1,%2,%3};"          \
        : "+f"((d)[0]), "+f"((d)[1]), "+f"((d)[2]), "+f"((d)[3])         \
        : "r"(a0), "r"(a1), "r"(a2), "r"(a3), "r"(b0), "r"(b1))

__device__ __forceinline__ uint32_t pack_h2(float a, float b) {
    __half2 h = __floats2half2_rn(a, b);
    return *(uint32_t*)&h;
}
__device__ __forceinline__ float bfly4(float v) {
    v += __shfl_xor_sync(0xffffffffu, v, 1);
    v += __shfl_xor_sync(0xffffffffu, v, 2);
    return v;
}
__device__ __forceinline__ float dot4(const float* c, const float* w) {
    return fmaf(c[0], w[0], fmaf(c[1], w[1], fmaf(c[2], w[2], c[3] * w[3])));
}

// ---------------- column reorder map ----------------
__device__ __forceinline__ int orig_k(int g, int m) {
    if (g < 32)  return         m * 32 + g;
    if (g < 64)  return  512 +  m * 32 + (g - 32);
    if (g < 80)  return 1024 +  m * 16 + (g - 64);
    if (g < 96)  return 1280 +  m * 16 + (g - 80);
    return              1536 +  m * 16 + (g - 96);
}

// ---------------- prep: We2 -> fp16 chunk blobs + zero accumulators ----------------
__global__ void prep_kernel(const float* __restrict__ We2) {
    int idx = blockIdx.x * blockDim.x + threadIdx.x;
    if (idx < 128 * 1792) {
        int k   = idx / 1792;
        int col = idx - k * 1792;
        int g, m;
        if (col < 512)       { g = col & 31;                m = col >> 5; }
        else if (col < 1024) { int u = col - 512;  g = 32 + (u & 31); m = u >> 5; }
        else if (col < 1280) { int u = col - 1024; g = 64 + (u & 15); m = u >> 4; }
        else if (col < 1536) { int u = col - 1280; g = 80 + (u & 15); m = u >> 4; }
        else                 { int u = col - 1536; g = 96 + (u & 15); m = u >> 4; }
        int rc = g * 16 + m;
        int c  = rc >> 5;
        int n  = rc & 31;
        g_W2h[c * 4352 + n * 136 + k] = __float2half_rn(We2[idx]);
    } else {
        int idx2 = idx - 128 * 1792;
        if (idx2 < NCHUNK * 32 * 8) {
            int c  = idx2 >> 8;
            int r2 = idx2 & 255;
            int n  = r2 >> 3;
            int kk = 128 + (r2 & 7);
            g_W2h[c * 4352 + n * 136 + kk] = __float2half_rn(0.f);
        }
    }
    // zero accumulators (grid-stride; replaces separate memset nodes)
    int total = gridDim.x * blockDim.x;
    for (int z = idx; z < 80 * NNODES; z += total) g_acc[z] = 0.f;
    for (int z = idx; z < NNODES; z += total)      g_cnt[z] = 0.f;
}

// ---------------- fused main kernel (2 CTAs/SM, 3 chunk-parts per edge tile) ----------------
__global__ __launch_bounds__(NTHREADS, 2)
void conv_main_kernel(const int*   __restrict__ dst,
                      const float* __restrict__ x_src,
                      const float* __restrict__ sh,
                      const float* __restrict__ edge_attr,
                      const float* __restrict__ We1,
                      const float* __restrict__ be1,
                      const float* __restrict__ be2,
                      int E)
{
    extern __shared__ char smem[];
    const uint32_t sbase = smem_u32(smem);
    const int tid  = threadIdx.x;
    const int wid  = tid >> 5, lane = tid & 31;
    const int qr   = lane >> 2, qc = lane & 3;
    const int tile = blockIdx.x / NPARTS;
    const int part = blockIdx.x - tile * NPARTS;
    const int e0   = tile * TE;
    const int cs   = (part == 0) ? 0  : ((part == 1) ? 19 : 38);
    const int ce   = (part == 0) ? 19 : ((part == 1) ? 38 : 56);

    float* be2_s = (float*)(smem + OFF_BE2);
    int*   dst_s = (int*)  (smem + OFF_DST);
    float* be1_s = (float*)(smem + OFF_BE1);
    float* w1s_s = (float*)(smem + OFF_W1S);
    float* msg_s = (float*)(smem + OFF_MSG);

    // ---- B chunk cs/cs+1 prefetch immediately (slots 0,1) ----
    {
        const char* s0p = (const char*)(g_W2h + (size_t)cs * 4352);
        for (int i = tid; i < 544; i += NTHREADS)
            CP_ASYNC16(sbase + OFF_B + i * 16, s0p + i * 16);
        CP_COMMIT();
        const char* s1p = (const char*)(g_W2h + (size_t)(cs + 1) * 4352);
        for (int i = tid; i < 544; i += NTHREADS)
            CP_ASYNC16(sbase + OFF_B + 8704 + i * 16, s1p + i * 16);
        CP_COMMIT();
    }

    // ---- phase 0 ----
    for (int idx = tid; idx < 128 * 16; idx += NTHREADS) {      // ea -> fp16 [e][40]
        int e = idx >> 4, dp = idx & 15;
        int eg = e0 + e;
        float v0 = 0.f, v1 = 0.f;
        if (eg < E) {
            const float* p = edge_attr + (size_t)eg * 32 + 2 * dp;
            v0 = p[0]; v1 = p[1];
        }
        *(uint32_t*)(smem + OFF_EAH + (uint32_t)(e * 40 + 2 * dp) * 2u) = pack_h2(v0, v1);
    }
    for (int idx = tid; idx < 4096; idx += NTHREADS) {          // We1 stage f32 [32][129]
        int d = idx >> 7, h = idx & 127;
        w1s_s[d * 129 + h] = We1[idx];
    }
    if (tid < 128) be1_s[tid] = be1[tid];
    for (int idx = tid; idx < 1792; idx += NTHREADS)
        be2_s[idx] = be2[orig_k(idx >> 4, idx & 15)];
    if (tid < 128) {
        int eg = e0 + tid;
        int dv = (eg < E) ? dst[eg] : 0;
        dst_s[tid] = dv;
        if (part == 0 && eg < E) atomicAdd(&g_cnt[dv], 1.f);   // count each edge once
    }
    __syncthreads();

    // ---- We1 transpose -> fp16 [h][40] ----
    for (int idx = tid; idx < 128 * 16; idx += NTHREADS) {
        int h = idx >> 4, dp = idx & 15;
        int d0 = 2 * dp;
        float v0 = w1s_s[d0 * 129 + h];
        float v1 = w1s_s[(d0 + 1) * 129 + h];
        *(uint32_t*)(smem + OFF_W1H + (uint32_t)(h * 40 + d0) * 2u) = pack_h2(v0, v1);
    }
    __syncthreads();

    // ---- H = relu(ea@We1+be1) via MMA -> A (fp16 [e][136]) ----
    {
        float hacc[16][4];
        #pragma unroll
        for (int nt = 0; nt < 16; nt++) {
            hacc[nt][0] = 0.f; hacc[nt][1] = 0.f;
            hacc[nt][2] = 0.f; hacc[nt][3] = 0.f;
        }
        uint32_t abase = sbase + OFF_EAH
                       + (uint32_t)(wid * 16 + (lane & 15)) * 80u
                       + (uint32_t)(lane >> 4) * 16u;
        uint32_t g2 = (uint32_t)(lane >> 3);
        uint32_t r8 = (uint32_t)(lane & 7);
        #pragma unroll
        for (int ks = 0; ks < 2; ks++) {
            uint32_t af0, af1, af2, af3;
            LDSM_X4(af0, af1, af2, af3, abase + (uint32_t)ks * 32u);
            #pragma unroll
            for (int p = 0; p < 8; p++) {
                uint32_t bb[4];
                uint32_t baddr = sbase + OFF_W1H
                               + ((2u * p + (g2 >> 1)) * 8u + r8) * 80u
                               + (g2 & 1u) * 16u + (uint32_t)ks * 32u;
                LDSM_X4(bb[0], bb[1], bb[2], bb[3], baddr);
                MMA16816(hacc[2*p],   af0, af1, af2, af3, bb[0], bb[1]);
                MMA16816(hacc[2*p+1], af0, af1, af2, af3, bb[2], bb[3]);
            }
        }
        uint32_t arow0 = (uint32_t)(wid * 16 + qr);
        #pragma unroll
        for (int nt = 0; nt < 16; nt++) {
            int h0 = nt * 8 + 2 * qc;
            float bx = be1_s[h0], by = be1_s[h0 + 1];
            float v0 = fmaxf(hacc[nt][0] + bx, 0.f);
            float v1 = fmaxf(hacc[nt][1] + by, 0.f);
            float v2 = fmaxf(hacc[nt][2] + bx, 0.f);
            float v3 = fmaxf(hacc[nt][3] + by, 0.f);
            *(uint32_t*)(smem + OFF_A + (arow0 * 136u + (uint32_t)h0) * 2u)        = pack_h2(v0, v1);
            *(uint32_t*)(smem + OFF_A + ((arow0 + 8u) * 136u + (uint32_t)h0) * 2u) = pack_h2(v2, v3);
        }
    }

    // ---- compact per-edge scalars/coeffs in regs (from global) ----
    const int e_lo = wid * 16 + qr;
    float CS[2][4], CD[2][4];
    float KSS[2], KVS[2], V2SEL[2], V2X[2], V2Y[2], V2Z[2];
    #pragma unroll
    for (int ei = 0; ei < 2; ei++) {
        int eg = e0 + e_lo + 8 * ei;
        if (eg < E) {
            const float* xp = x_src + (size_t)eg * 64;
            float4 shv = __ldg((const float4*)(sh + (size_t)eg * 4));
            float s2v = shv.x, v2x = shv.y, v2y = shv.z, v2z = shv.w;
            KSS[ei] = C_A0 * s2v;
            KVS[ei] = C_A1 * s2v;
            V2X[ei] = v2x; V2Y[ei] = v2y; V2Z[ei] = v2z;
            V2SEL[ei] = (qc == 0) ? v2x : ((qc == 1) ? v2y : v2z);
            float2 sA = __ldg((const float2*)(xp + 2 * qc));
            float2 sB = __ldg((const float2*)(xp + 8 + 2 * qc));
            CS[ei][0] = sA.x; CS[ei][1] = sA.y;
            CS[ei][2] = sB.x; CS[ei][3] = sB.y;
            #pragma unroll
            for (int i = 0; i < 4; i++) {
                int m = (i >> 1) * 8 + 2 * qc + (i & 1);
                float x = __ldg(xp + 16 + 3 * m);
                float y = __ldg(xp + 17 + 3 * m);
                float z = __ldg(xp + 18 + 3 * m);
                CD[ei][i] = x * v2x + y * v2y + z * v2z;
            }
        } else {
            KSS[ei] = 0.f; KVS[ei] = 0.f; V2SEL[ei] = 0.f;
            V2X[ei] = 0.f; V2Y[ei] = 0.f; V2Z[ei] = 0.f;
            #pragma unroll
            for (int i = 0; i < 4; i++) { CS[ei][i] = 0.f; CD[ei][i] = 0.f; }
        }
    }
    __syncthreads();   // A tile complete; phase-0 overlays dead

    // ---- A fragment preload (resident across all chunks) ----
    uint32_t AH[8][4];
    {
        uint32_t arow = (uint32_t)(wid * 16 + (lane & 15));
        uint32_t acol = (uint32_t)(lane >> 4) * 16u;
        uint32_t ah = sbase + OFF_A + arow * 272u + acol;
        #pragma unroll
        for (int ks = 0; ks < 8; ks++)
            LDSM_X4(AH[ks][0], AH[ks][1], AH[ks][2], AH[ks][3], ah + ks * 32u);
    }
    __syncthreads();   // all A reads done -> A region reusable as v1 tile

    // ---- v1 tile into A region ([e][52] f32), zero msg ----
    float* v1_s = (float*)(smem + OFF_A);
    for (int idx = tid; idx < 128 * 48; idx += NTHREADS) {
        int e = idx / 48, j = idx - (idx / 48) * 48;
        int eg = e0 + e;
        v1_s[e * 52 + j] = (eg < E) ? x_src[(size_t)eg * 64 + 16 + j] : 0.f;
    }
    for (int idx = tid; idx < 128 * 81; idx += NTHREADS) msg_s[idx] = 0.f;
    __syncthreads();

    float* msg_lo = &msg_s[e_lo * 81];
    float* msg_hi = &msg_s[(e_lo + 8) * 81];
    const float* xs0 = &v1_s[e_lo * 52];
    const float* xs1 = &v1_s[(e_lo + 8) * 52];

    // B ldmatrix lane offsets (32-row tile: pairs p=0,1 cover n-tiles 0..3)
    uint32_t bl_off[2];
    {
        uint32_t g2 = (uint32_t)(lane >> 3);
        uint32_t r8 = (uint32_t)(lane & 7);
        #pragma unroll
        for (int p = 0; p < 2; p++)
            bl_off[p] = ((2u * p + (g2 >> 1)) * 8u + r8) * 272u + (g2 & 1u) * 16u;
    }

    // ---- mainloop: chunks [cs, ce), 3-slot ring, distance-2 prefetch ----
    #pragma unroll 1
    for (int c = cs; c < ce; c++) {
        const int lc = c - cs;
        if (c < ce - 1) asm volatile("cp.async.wait_group 1;" ::: "memory");
        else            asm volatile("cp.async.wait_group 0;" ::: "memory");
        __syncthreads();   // B(c) visible; slot (lc+2)%3 fully consumed

        if (c + 2 < ce) {
            const char* src = (const char*)(g_W2h + (size_t)(c + 2) * 4352);
            uint32_t dstb = sbase + OFF_B + (uint32_t)((lc + 2) % 3) * 8704u;
            for (int i = tid; i < 544; i += NTHREADS)
                CP_ASYNC16(dstb + i * 16, src + i * 16);
            CP_COMMIT();
        }

        const uint32_t bbuf = sbase + OFF_B + (uint32_t)(lc % 3) * 8704u;

        float acc[4][4];
        #pragma unroll
        for (int nt = 0; nt < 4; nt++) {
            acc[nt][0] = 0.f; acc[nt][1] = 0.f;
            acc[nt][2] = 0.f; acc[nt][3] = 0.f;
        }
        #pragma unroll
        for (int ks = 0; ks < 8; ks++) {
            uint32_t b[4][2];
            LDSM_X4(b[0][0], b[0][1], b[1][0], b[1][1],
                    bbuf + bl_off[0] + (uint32_t)ks * 32u);
            LDSM_X4(b[2][0], b[2][1], b[3][0], b[3][1],
                    bbuf + bl_off[1] + (uint32_t)ks * 32u);
            #pragma unroll
            for (int nt = 0; nt < 4; nt++)
                MMA16816(acc[nt], AH[ks][0], AH[ks][1], AH[ks][2], AH[ks][3],
                         b[nt][0], b[nt][1]);
        }

        // ---- epilogue: 2 groups, type by global chunk index ----
        #pragma unroll
        for (int t = 0; t < 2; t++) {
            const int g = c * 2 + t;
            const float* bp = &be2_s[g * 16 + 2 * qc];
            float b0 = bp[0], b1 = bp[1], b2 = bp[8], b3 = bp[9];
            float w0[4] = { acc[2*t][0] + b0, acc[2*t][1] + b1,
                            acc[2*t+1][0] + b2, acc[2*t+1][1] + b3 };
            float w1[4] = { acc[2*t][2] + b0, acc[2*t][3] + b1,
                            acc[2*t+1][2] + b2, acc[2*t+1][3] + b3 };

            if (c < 16) {                        // ss
                float p0 = bfly4(dot4(CS[0], w0));
                float p1 = bfly4(dot4(CS[1], w1));
                if (qc == 0) {
                    msg_lo[g] += KSS[0] * p0;
                    msg_hi[g] += KSS[1] * p1;
                }
            } else if (c < 32) {                 // vv0
                float p0 = bfly4(dot4(CD[0], w0));
                float p1 = bfly4(dot4(CD[1], w1));
                if (qc == 0) {
                    msg_lo[g - 32] += C_A0I3 * p0;
                    msg_hi[g - 32] += C_A0I3 * p1;
                }
            } else if (c < 40) {                 // sv
                float p0 = bfly4(dot4(CS[0], w0));
                float p1 = bfly4(dot4(CS[1], w1));
                if (qc < 3) {
                    int o = 32 + 3 * (g - 64) + qc;
                    msg_lo[o] += C_A1 * p0 * V2SEL[0];
                    msg_hi[o] += C_A1 * p1 * V2SEL[1];
                }
            } else if (c < 48) {                 // vs: v1 from smem
                float px0 = 0.f, py0 = 0.f, pz0 = 0.f;
                float px1 = 0.f, py1 = 0.f, pz1 = 0.f;
                #pragma unroll
                for (int i = 0; i < 4; i++) {
                    int m = (i >> 1) * 8 + 2 * qc + (i & 1);
                    const float* v0p = xs0 + 3 * m;
                    const float* v1p = xs1 + 3 * m;
                    px0 = fmaf(v0p[0], w0[i], px0);
                    py0 = fmaf(v0p[1], w0[i], py0);
                    pz0 = fmaf(v0p[2], w0[i], pz0);
                    px1 = fmaf(v1p[0], w1[i], px1);
                    py1 = fmaf(v1p[1], w1[i], py1);
                    pz1 = fmaf(v1p[2], w1[i], pz1);
                }
                px0 = bfly4(px0); py0 = bfly4(py0); pz0 = bfly4(pz0);
                px1 = bfly4(px1); py1 = bfly4(py1); pz1 = bfly4(pz1);
                if (qc < 3) {
                    float ps0 = (qc == 0) ? px0 : ((qc == 1) ? py0 : pz0);
                    float ps1 = (qc == 0) ? px1 : ((qc == 1) ? py1 : pz1);
                    int o = 32 + 3 * (g - 80) + qc;
                    msg_lo[o] += KVS[0] * ps0;
                    msg_hi[o] += KVS[1] * ps1;
                }
            } else {                             // vv1: cross(v1,v2) on the fly
                float px0 = 0.f, py0 = 0.f, pz0 = 0.f;
                float px1 = 0.f, py1 = 0.f, pz1 = 0.f;
                #pragma unroll
                for (int i = 0; i < 4; i++) {
                    int m = (i >> 1) * 8 + 2 * qc + (i & 1);
                    const float* v0p = xs0 + 3 * m;
                    float cx = v0p[1] * V2Z[0] - v0p[2] * V2Y[0];
                    float cy = v0p[2] * V2X[0] - v0p[0] * V2Z[0];
                    float cz = v0p[0] * V2Y[0] - v0p[1] * V2X[0];
                    px0 = fmaf(cx, w0[i], px0);
                    py0 = fmaf(cy, w0[i], py0);
                    pz0 = fmaf(cz, w0[i], pz0);
                    const float* v1p = xs1 + 3 * m;
                    float dx = v1p[1] * V2Z[1] - v1p[2] * V2Y[1];
                    float dy = v1p[2] * V2X[1] - v1p[0] * V2Z[1];
                    float dz = v1p[0] * V2Y[1] - v1p[1] * V2X[1];
                    px1 = fmaf(dx, w1[i], px1);
                    py1 = fmaf(dy, w1[i], py1);
                    pz1 = fmaf(dz, w1[i], pz1);
                }
                px0 = bfly4(px0); py0 = bfly4(py0); pz0 = bfly4(pz0);
                px1 = bfly4(px1); py1 = bfly4(py1); pz1 = bfly4(pz1);
                if (qc < 3) {
                    float ps0 = (qc == 0) ? px0 : ((qc == 1) ? py0 : pz0);
                    float ps1 = (qc == 0) ? px1 : ((qc == 1) ? py1 : pz1);
                    int o = 32 + 3 * (g - 96) + qc;
                    msg_lo[o] += C_A1I2 * ps0;
                    msg_hi[o] += C_A1I2 * ps1;
                }
            }
        }
    }
    __syncthreads();

    // ---- final scatter: only this part's j-window ----
    // part 0: groups 0..37  -> j in [0,32)
    // part 1: groups 38..75 -> j in [6,68)
    // part 2: groups 76..111-> j in [32,80)
    const int j0 = (part == 0) ? 0  : ((part == 1) ? 6  : 32);
    const int jw = (part == 0) ? 32 : ((part == 1) ? 62 : 48);
    for (int idx = tid; idx < 128 * jw; idx += NTHREADS) {
        int e = idx / jw;
        int j = j0 + (idx - e * jw);
        if (e0 + e < E)
            atomicAdd(&g_acc[j * NNODES + dst_s[e]], msg_s[e * 81 + j]);
    }
}

// ---------------- finalize: 64 nodes/block, 4 roles/node ----------------
__global__ __launch_bounds__(256)
void finalize_kernel(const float* __restrict__ x_dst,
                     const float* __restrict__ Wr0,
                     const float* __restrict__ Wr1,
                     float* __restrict__ out, int N)
{
    __shared__ float msg_s[80 * 64];
    __shared__ float gate_s[64 * 17];
    __shared__ float cnt_s[64];
    __shared__ float Wr0_s[512];
    __shared__ float Wr1_s[256];

    const int tid  = threadIdx.x;
    const int n0   = blockIdx.x * 64;
    const int role = tid >> 6;        // 0: scalars, 1: gates, 2: vec o0-7, 3: vec o8-15
    const int nl   = tid & 63;
    const int n    = n0 + nl;
    const bool valid = (n < N);

    for (int idx = tid; idx < 1280; idx += 256) {
        int j = idx >> 4, t4 = (idx & 15) * 4;
        int nn = n0 + t4;
        float4 v = make_float4(0.f, 0.f, 0.f, 0.f);
        if (nn + 3 < N) {
            v = *(const float4*)&g_acc[j * NNODES + nn];
        } else {
            if (nn + 0 < N) v.x = g_acc[j * NNODES + nn + 0];
            if (nn + 1 < N) v.y = g_acc[j * NNODES + nn + 1];
            if (nn + 2 < N) v.z = g_acc[j * NNODES + nn + 2];
            if (nn + 3 < N) v.w = g_acc[j * NNODES + nn + 3];
        }
        *(float4*)&msg_s[j * 64 + t4] = v;
    }
    if (tid < 64) {
        int nn = n0 + tid;
        cnt_s[tid] = (nn < N) ? g_cnt[nn] : 1.f;
    }
    for (int idx = tid; idx < 512; idx += 256) Wr0_s[idx] = Wr0[idx];
    if (tid < 256) Wr1_s[tid] = Wr1[tid];
    __syncthreads();

    const float inv = 1.f / fmaxf(cnt_s[nl], 1.f);
    const float* xd = x_dst + (size_t)n * 64;
    float* op = out + (size_t)n * 64;

    float vtx[8], vty[8], vtz[8];

    if (role == 0) {
        if (valid) {
            float sd[16];
            #pragma unroll
            for (int i = 0; i < 4; i++) {
                float4 v = __ldg((const float4*)(xd + 4 * i));
                sd[4*i] = v.x; sd[4*i+1] = v.y; sd[4*i+2] = v.z; sd[4*i+3] = v.w;
            }
            #pragma unroll 4
            for (int o = 0; o < 16; o++) {
                float t = 0.f;
                #pragma unroll
                for (int m = 0; m < 16; m++) t = fmaf(sd[m], Wr0_s[m * 32 + o], t);
                op[o] = fmaxf(msg_s[o * 64 + nl] * inv + 0.25f * t, 0.f);
            }
        }
    } else if (role == 1) {
        if (valid) {
            float sd[16];
            #pragma unroll
            for (int i = 0; i < 4; i++) {
                float4 v = __ldg((const float4*)(xd + 4 * i));
                sd[4*i] = v.x; sd[4*i+1] = v.y; sd[4*i+2] = v.z; sd[4*i+3] = v.w;
            }
            #pragma unroll 4
            for (int o = 0; o < 16; o++) {
                float t = 0.f;
                #pragma unroll
                for (int m = 0; m < 16; m++) t = fmaf(sd[m], Wr0_s[m * 32 + 16 + o], t);
                float v = msg_s[(16 + o) * 64 + nl] * inv + 0.25f * t;
                gate_s[nl * 17 + o] = 1.f / (1.f + expf(-v));
            }
        }
    } else {
        if (valid) {
            float vd[48];
            #pragma unroll
            for (int i = 0; i < 12; i++) {
                float4 v = __ldg((const float4*)(xd + 16 + 4 * i));
                vd[4*i] = v.x; vd[4*i+1] = v.y; vd[4*i+2] = v.z; vd[4*i+3] = v.w;
            }
            const int ob = (role - 2) * 8;
            #pragma unroll
            for (int oo = 0; oo < 8; oo++) {
                int o = ob + oo;
                float tx = 0.f, ty = 0.f, tz = 0.f;
                #pragma unroll
                for (int m = 0; m < 16; m++) {
                    float w = Wr1_s[m * 16 + o];
                    tx = fmaf(vd[3*m+0], w, tx);
                    ty = fmaf(vd[3*m+1], w, ty);
                    tz = fmaf(vd[3*m+2], w, tz);
                }
                vtx[oo] = tx; vty[oo] = ty; vtz[oo] = tz;
            }
        }
    }
    __syncthreads();

    if (role >= 2 && valid) {
        const int ob = (role - 2) * 8;
        #pragma unroll
        for (int oo = 0; oo < 8; oo++) {
            int o = ob + oo;
            float g = gate_s[nl * 17 + o];
            int jb = 32 + 3 * o;
            op[16 + 3*o + 0] = (msg_s[(jb + 0) * 64 + nl] * inv + 0.25f * vtx[oo]) * g;
            op[16 + 3*o + 1] = (msg_s[(jb + 1) * 64 + nl] * inv + 0.25f * vty[oo]) * g;
            op[16 + 3*o + 2] = (msg_s[(jb + 2) * 64 + nl] * inv + 0.25f * vtz[oo]) * g;
        }
    }
}

// ---------------- launch ----------------
extern "C" void kernel_launch(void* const* d_in, const int* in_sizes, int n_in,
                              void* d_out, int out_size)
{
    const int*   dst       = (const int*)  d_in[0];
    const float* x_src     = (const float*)d_in[1];
    const float* x_dst     = (const float*)d_in[2];
    const float* sh        = (const float*)d_in[3];
    const float* edge_attr = (const float*)d_in[4];
    const float* We1       = (const float*)d_in[5];
    const float* be1       = (const float*)d_in[6];
    const float* We2       = (const float*)d_in[7];
    const float* be2       = (const float*)d_in[8];
    const float* Wr0       = (const float*)d_in[9];
    const float* Wr1       = (const float*)d_in[10];
    float* out = (float*)d_out;

    int E = in_sizes[0];
    int N = in_sizes[2] / 64;

    cudaFuncSetAttribute(conv_main_kernel,
                         cudaFuncAttributeMaxDynamicSharedMemorySize, SMEM_TOT);

    int prep_total = 128 * 1792 + NCHUNK * 32 * 8;
    prep_kernel<<<(prep_total + 255) / 256, 256>>>(We2);
    int nb = (E + TE - 1) / TE;
    conv_main_kernel<<<nb * NPARTS, NTHREADS, SMEM_TOT>>>(dst, x_src, sh, edge_attr,
                                                          We1, be1, be2, E);
    finalize_kernel<<<(N + 63) / 64, 256>>>(x_dst, Wr0, Wr1, out, N);
}

// round 17
// speedup vs baseline: 1.2020x; 1.2020x over previous
#include <cuda_runtime.h>
#include <cuda_fp16.h>
#include <cstdint>
#include <math.h>

#define TE        128
#define NTHREADS  256
#define NCHUNK    56       // 1792 cols / 32 per chunk
#define NNODES    10000

#define C_A0      0.17677669529663687f   // 1/sqrt(2*16)
#define C_A0I3    0.10206207261596575f   // A0/sqrt(3)
#define C_A1      0.14433756729740643f   // 1/sqrt(3*16)
#define C_A1I2    0.10206207261596577f   // A1/sqrt(2)

// ---------------- smem byte offsets (SMEM_TOT = 110592 -> 2 CTAs/SM) ----------------
#define OFF_B     0         // 3 x (32 x 136 fp16) = 3 x 8704 = 26112
#define OFF_A     26112     // A-tile 128x136 fp16 = 34816; later v1 tile 128x52 f32 = 26624
#define OFF_MSG   60928     // 128 x 81 f32 = 41472 (phase0 overlay below)
#define OFF_EAH   60928     // ea fp16 [e][40] = 10240
#define OFF_W1H   71168     // We1 fp16 [h][40] = 10240
#define OFF_W1S   81408     // We1 f32 stage [32][129] = 16512  (ends 97920 < 102400)
#define OFF_BE2   102400    // 1792 f32 = 7168
#define OFF_BE1   109568    // 128 f32 = 512
#define OFF_DST   110080    // 128 int = 512
#define SMEM_TOT  110592

// ---------------- device scratch ----------------
__device__ float  g_acc[80 * NNODES];      // [j][n] layout
__device__ float  g_cnt[NNODES];
__device__ __half g_W2h[NCHUNK * 4352];    // per chunk: [n=32][k=136] fp16

// ---------------- helpers ----------------
__device__ __forceinline__ uint32_t smem_u32(const void* p) {
    uint32_t a;
    asm("{ .reg .u64 t; cvta.to.shared.u64 t, %1; cvt.u32.u64 %0, t; }" : "=r"(a) : "l"(p));
    return a;
}
#define CP_ASYNC16(d, s)  asm volatile("cp.async.cg.shared.global [%0], [%1], 16;" :: "r"(d), "l"(s) : "memory")
#define CP_COMMIT()       asm volatile("cp.async.commit_group;" ::: "memory")

#define LDSM_X4(r0, r1, r2, r3, addr)                                          \
    asm volatile("ldmatrix.sync.aligned.m8n8.x4.shared.b16 {%0,%1,%2,%3}, [%4];" \
        : "=r"(r0), "=r"(r1), "=r"(r2), "=r"(r3) : "r"(addr))

#define MMA16816(d, a0,a1,a2,a3, b0,b1)                                   \
    asm volatile("mma.sync.aligned.m16n8k16.row.col.f32.f16.f16.f32 "    \
        "{%0,%1,%2,%3}, {%4,%5,%6,%7}, {%8,%9}, {%0,%1,%2,%3};"          \
        : "+f"((d)[0]), "+f"((d)[1]), "+f"((d)[2]), "+f"((d)[3])         \
        : "r"(a0), "r"(a1), "r"(a2), "r"(a3), "r"(b0), "r"(b1))

__device__ __forceinline__ uint32_t pack_h2(float a, float b) {
    __half2 h = __floats2half2_rn(a, b);
    return *(uint32_t*)&h;
}
__device__ __forceinline__ float bfly4(float v) {
    v += __shfl_xor_sync(0xffffffffu, v, 1);
    v += __shfl_xor_sync(0xffffffffu, v, 2);
    return v;
}
__device__ __forceinline__ float dot4(const float* c, const float* w) {
    return fmaf(c[0], w[0], fmaf(c[1], w[1], fmaf(c[2], w[2], c[3] * w[3])));
}

// ---------------- column reorder map ----------------
__device__ __forceinline__ int orig_k(int g, int m) {
    if (g < 32)  return         m * 32 + g;
    if (g < 64)  return  512 +  m * 32 + (g - 32);
    if (g < 80)  return 1024 +  m * 16 + (g - 64);
    if (g < 96)  return 1280 +  m * 16 + (g - 80);
    return              1536 +  m * 16 + (g - 96);
}

// ---------------- prep: We2 -> fp16 chunk blobs + zero accumulators ----------------
__global__ void prep_kernel(const float* __restrict__ We2) {
    int idx = blockIdx.x * blockDim.x + threadIdx.x;
    if (idx < 128 * 1792) {
        int k   = idx / 1792;
        int col = idx - k * 1792;
        int g, m;
        if (col < 512)       { g = col & 31;                m = col >> 5; }
        else if (col < 1024) { int u = col - 512;  g = 32 + (u & 31); m = u >> 5; }
        else if (col < 1280) { int u = col - 1024; g = 64 + (u & 15); m = u >> 4; }
        else if (col < 1536) { int u = col - 1280; g = 80 + (u & 15); m = u >> 4; }
        else                 { int u = col - 1536; g = 96 + (u & 15); m = u >> 4; }
        int rc = g * 16 + m;
        int c  = rc >> 5;
        int n  = rc & 31;
        g_W2h[c * 4352 + n * 136 + k] = __float2half_rn(We2[idx]);
    } else {
        int idx2 = idx - 128 * 1792;
        if (idx2 < NCHUNK * 32 * 8) {
            int c  = idx2 >> 8;
            int r2 = idx2 & 255;
            int n  = r2 >> 3;
            int kk = 128 + (r2 & 7);
            g_W2h[c * 4352 + n * 136 + kk] = __float2half_rn(0.f);
        }
    }
    // zero accumulators (grid-stride; replaces separate memset nodes)
    int total = gridDim.x * blockDim.x;
    for (int z = idx; z < 80 * NNODES; z += total) g_acc[z] = 0.f;
    for (int z = idx; z < NNODES; z += total)      g_cnt[z] = 0.f;
}

// ---------------- fused main kernel (2 CTAs/SM) ----------------
__global__ __launch_bounds__(NTHREADS, 2)
void conv_main_kernel(const int*   __restrict__ dst,
                      const float* __restrict__ x_src,
                      const float* __restrict__ sh,
                      const float* __restrict__ edge_attr,
                      const float* __restrict__ We1,
                      const float* __restrict__ be1,
                      const float* __restrict__ be2,
                      int E)
{
    extern __shared__ char smem[];
    const uint32_t sbase = smem_u32(smem);
    const int tid  = threadIdx.x;
    const int wid  = tid >> 5, lane = tid & 31;
    const int qr   = lane >> 2, qc = lane & 3;
    const int e0   = blockIdx.x * TE;

    float* be2_s = (float*)(smem + OFF_BE2);
    int*   dst_s = (int*)  (smem + OFF_DST);
    float* be1_s = (float*)(smem + OFF_BE1);
    float* w1s_s = (float*)(smem + OFF_W1S);
    float* msg_s = (float*)(smem + OFF_MSG);

    // ---- B chunk 0/1 prefetch immediately (slots 0,1) ----
    {
        const char* s0p = (const char*)g_W2h;
        for (int i = tid; i < 544; i += NTHREADS)
            CP_ASYNC16(sbase + OFF_B + i * 16, s0p + i * 16);
        CP_COMMIT();
        const char* s1p = (const char*)g_W2h + 8704;
        for (int i = tid; i < 544; i += NTHREADS)
            CP_ASYNC16(sbase + OFF_B + 8704 + i * 16, s1p + i * 16);
        CP_COMMIT();
    }

    // ---- phase 0 ----
    for (int idx = tid; idx < 128 * 16; idx += NTHREADS) {      // ea -> fp16 [e][40]
        int e = idx >> 4, dp = idx & 15;
        int eg = e0 + e;
        float v0 = 0.f, v1 = 0.f;
        if (eg < E) {
            const float* p = edge_attr + (size_t)eg * 32 + 2 * dp;
            v0 = p[0]; v1 = p[1];
        }
        *(uint32_t*)(smem + OFF_EAH + (uint32_t)(e * 40 + 2 * dp) * 2u) = pack_h2(v0, v1);
    }
    for (int idx = tid; idx < 4096; idx += NTHREADS) {          // We1 stage f32 [32][129]
        int d = idx >> 7, h = idx & 127;
        w1s_s[d * 129 + h] = We1[idx];
    }
    if (tid < 128) be1_s[tid] = be1[tid];
    for (int idx = tid; idx < 1792; idx += NTHREADS)
        be2_s[idx] = be2[orig_k(idx >> 4, idx & 15)];
    if (tid < 128) {
        int eg = e0 + tid;
        int dv = (eg < E) ? dst[eg] : 0;
        dst_s[tid] = dv;
        if (eg < E) atomicAdd(&g_cnt[dv], 1.f);
    }
    __syncthreads();

    // ---- We1 transpose -> fp16 [h][40] ----
    for (int idx = tid; idx < 128 * 16; idx += NTHREADS) {
        int h = idx >> 4, dp = idx & 15;
        int d0 = 2 * dp;
        float v0 = w1s_s[d0 * 129 + h];
        float v1 = w1s_s[(d0 + 1) * 129 + h];
        *(uint32_t*)(smem + OFF_W1H + (uint32_t)(h * 40 + d0) * 2u) = pack_h2(v0, v1);
    }
    __syncthreads();

    // ---- H = relu(ea@We1+be1) via MMA -> A (fp16 [e][136]) ----
    {
        float hacc[16][4];
        #pragma unroll
        for (int nt = 0; nt < 16; nt++) {
            hacc[nt][0] = 0.f; hacc[nt][1] = 0.f;
            hacc[nt][2] = 0.f; hacc[nt][3] = 0.f;
        }
        uint32_t abase = sbase + OFF_EAH
                       + (uint32_t)(wid * 16 + (lane & 15)) * 80u
                       + (uint32_t)(lane >> 4) * 16u;
        uint32_t g2 = (uint32_t)(lane >> 3);
        uint32_t r8 = (uint32_t)(lane & 7);
        #pragma unroll
        for (int ks = 0; ks < 2; ks++) {
            uint32_t af0, af1, af2, af3;
            LDSM_X4(af0, af1, af2, af3, abase + (uint32_t)ks * 32u);
            #pragma unroll
            for (int p = 0; p < 8; p++) {
                uint32_t bb[4];
                uint32_t baddr = sbase + OFF_W1H
                               + ((2u * p + (g2 >> 1)) * 8u + r8) * 80u
                               + (g2 & 1u) * 16u + (uint32_t)ks * 32u;
                LDSM_X4(bb[0], bb[1], bb[2], bb[3], baddr);
                MMA16816(hacc[2*p],   af0, af1, af2, af3, bb[0], bb[1]);
                MMA16816(hacc[2*p+1], af0, af1, af2, af3, bb[2], bb[3]);
            }
        }
        uint32_t arow0 = (uint32_t)(wid * 16 + qr);
        #pragma unroll
        for (int nt = 0; nt < 16; nt++) {
            int h0 = nt * 8 + 2 * qc;
            float bx = be1_s[h0], by = be1_s[h0 + 1];
            float v0 = fmaxf(hacc[nt][0] + bx, 0.f);
            float v1 = fmaxf(hacc[nt][1] + by, 0.f);
            float v2 = fmaxf(hacc[nt][2] + bx, 0.f);
            float v3 = fmaxf(hacc[nt][3] + by, 0.f);
            *(uint32_t*)(smem + OFF_A + (arow0 * 136u + (uint32_t)h0) * 2u)        = pack_h2(v0, v1);
            *(uint32_t*)(smem + OFF_A + ((arow0 + 8u) * 136u + (uint32_t)h0) * 2u) = pack_h2(v2, v3);
        }
    }

    // ---- compact per-edge scalars/coeffs in regs (from global) ----
    const int e_lo = wid * 16 + qr;
    float CS[2][4], CD[2][4];
    float KSS[2], KVS[2], V2SEL[2], V2X[2], V2Y[2], V2Z[2];
    #pragma unroll
    for (int ei = 0; ei < 2; ei++) {
        int eg = e0 + e_lo + 8 * ei;
        if (eg < E) {
            const float* xp = x_src + (size_t)eg * 64;
            float4 shv = __ldg((const float4*)(sh + (size_t)eg * 4));
            float s2v = shv.x, v2x = shv.y, v2y = shv.z, v2z = shv.w;
            KSS[ei] = C_A0 * s2v;
            KVS[ei] = C_A1 * s2v;
            V2X[ei] = v2x; V2Y[ei] = v2y; V2Z[ei] = v2z;
            V2SEL[ei] = (qc == 0) ? v2x : ((qc == 1) ? v2y : v2z);
            float2 sA = __ldg((const float2*)(xp + 2 * qc));
            float2 sB = __ldg((const float2*)(xp + 8 + 2 * qc));
            CS[ei][0] = sA.x; CS[ei][1] = sA.y;
            CS[ei][2] = sB.x; CS[ei][3] = sB.y;
            #pragma unroll
            for (int i = 0; i < 4; i++) {
                int m = (i >> 1) * 8 + 2 * qc + (i & 1);
                float x = __ldg(xp + 16 + 3 * m);
                float y = __ldg(xp + 17 + 3 * m);
                float z = __ldg(xp + 18 + 3 * m);
                CD[ei][i] = x * v2x + y * v2y + z * v2z;
            }
        } else {
            KSS[ei] = 0.f; KVS[ei] = 0.f; V2SEL[ei] = 0.f;
            V2X[ei] = 0.f; V2Y[ei] = 0.f; V2Z[ei] = 0.f;
            #pragma unroll
            for (int i = 0; i < 4; i++) { CS[ei][i] = 0.f; CD[ei][i] = 0.f; }
        }
    }
    __syncthreads();   // A tile complete; phase-0 overlays dead

    // ---- A fragment preload (resident across all chunks) ----
    uint32_t AH[8][4];
    {
        uint32_t arow = (uint32_t)(wid * 16 + (lane & 15));
        uint32_t acol = (uint32_t)(lane >> 4) * 16u;
        uint32_t ah = sbase + OFF_A + arow * 272u + acol;
        #pragma unroll
        for (int ks = 0; ks < 8; ks++)
            LDSM_X4(AH[ks][0], AH[ks][1], AH[ks][2], AH[ks][3], ah + ks * 32u);
    }
    __syncthreads();   // all A reads done -> A region reusable as v1 tile

    // ---- v1 tile into A region ([e][52] f32), zero msg ----
    float* v1_s = (float*)(smem + OFF_A);
    for (int idx = tid; idx < 128 * 48; idx += NTHREADS) {
        int e = idx / 48, j = idx - (idx / 48) * 48;
        int eg = e0 + e;
        v1_s[e * 52 + j] = (eg < E) ? x_src[(size_t)eg * 64 + 16 + j] : 0.f;
    }
    for (int idx = tid; idx < 128 * 81; idx += NTHREADS) msg_s[idx] = 0.f;
    __syncthreads();

    float* msg_lo = &msg_s[e_lo * 81];
    float* msg_hi = &msg_s[(e_lo + 8) * 81];
    const float* xs0 = &v1_s[e_lo * 52];
    const float* xs1 = &v1_s[(e_lo + 8) * 52];

    // B ldmatrix lane offsets (32-row tile: pairs p=0,1 cover n-tiles 0..3)
    uint32_t bl_off[2];
    {
        uint32_t g2 = (uint32_t)(lane >> 3);
        uint32_t r8 = (uint32_t)(lane & 7);
        #pragma unroll
        for (int p = 0; p < 2; p++)
            bl_off[p] = ((2u * p + (g2 >> 1)) * 8u + r8) * 272u + (g2 & 1u) * 16u;
    }

    // ---- mainloop: 56 chunks of 32 cols, 3-slot ring, distance-2 prefetch ----
    #pragma unroll 1
    for (int c = 0; c < NCHUNK; c++) {
        if (c < NCHUNK - 1) asm volatile("cp.async.wait_group 1;" ::: "memory");
        else                asm volatile("cp.async.wait_group 0;" ::: "memory");
        __syncthreads();   // B(c) visible; slot (c+2)%3 fully consumed (chunk c-1)

        if (c + 2 < NCHUNK) {
            const char* src = (const char*)g_W2h + (size_t)(c + 2) * 8704;
            uint32_t dstb = sbase + OFF_B + (uint32_t)((c + 2) % 3) * 8704u;
            for (int i = tid; i < 544; i += NTHREADS)
                CP_ASYNC16(dstb + i * 16, src + i * 16);
            CP_COMMIT();
        }

        const uint32_t bbuf = sbase + OFF_B + (uint32_t)(c % 3) * 8704u;

        float acc[4][4];
        #pragma unroll
        for (int nt = 0; nt < 4; nt++) {
            acc[nt][0] = 0.f; acc[nt][1] = 0.f;
            acc[nt][2] = 0.f; acc[nt][3] = 0.f;
        }
        #pragma unroll
        for (int ks = 0; ks < 8; ks++) {
            uint32_t b[4][2];
            LDSM_X4(b[0][0], b[0][1], b[1][0], b[1][1],
                    bbuf + bl_off[0] + (uint32_t)ks * 32u);
            LDSM_X4(b[2][0], b[2][1], b[3][0], b[3][1],
                    bbuf + bl_off[1] + (uint32_t)ks * 32u);
            #pragma unroll
            for (int nt = 0; nt < 4; nt++)
                MMA16816(acc[nt], AH[ks][0], AH[ks][1], AH[ks][2], AH[ks][3],
                         b[nt][0], b[nt][1]);
        }

        // ---- epilogue: 2 groups, type uniform per chunk ----
        #pragma unroll
        for (int t = 0; t < 2; t++) {
            const int g = c * 2 + t;
            const float* bp = &be2_s[g * 16 + 2 * qc];
            float b0 = bp[0], b1 = bp[1], b2 = bp[8], b3 = bp[9];
            float w0[4] = { acc[2*t][0] + b0, acc[2*t][1] + b1,
                            acc[2*t+1][0] + b2, acc[2*t+1][1] + b3 };
            float w1[4] = { acc[2*t][2] + b0, acc[2*t][3] + b1,
                            acc[2*t+1][2] + b2, acc[2*t+1][3] + b3 };

            if (c < 16) {                        // ss
                float p0 = bfly4(dot4(CS[0], w0));
                float p1 = bfly4(dot4(CS[1], w1));
                if (qc == 0) {
                    msg_lo[g] += KSS[0] * p0;
                    msg_hi[g] += KSS[1] * p1;
                }
            } else if (c < 32) {                 // vv0
                float p0 = bfly4(dot4(CD[0], w0));
                float p1 = bfly4(dot4(CD[1], w1));
                if (qc == 0) {
                    msg_lo[g - 32] += C_A0I3 * p0;
                    msg_hi[g - 32] += C_A0I3 * p1;
                }
            } else if (c < 40) {                 // sv
                float p0 = bfly4(dot4(CS[0], w0));
                float p1 = bfly4(dot4(CS[1], w1));
                if (qc < 3) {
                    int o = 32 + 3 * (g - 64) + qc;
                    msg_lo[o] += C_A1 * p0 * V2SEL[0];
                    msg_hi[o] += C_A1 * p1 * V2SEL[1];
                }
            } else if (c < 48) {                 // vs: v1 from smem
                float px0 = 0.f, py0 = 0.f, pz0 = 0.f;
                float px1 = 0.f, py1 = 0.f, pz1 = 0.f;
                #pragma unroll
                for (int i = 0; i < 4; i++) {
                    int m = (i >> 1) * 8 + 2 * qc + (i & 1);
                    const float* v0p = xs0 + 3 * m;
                    const float* v1p = xs1 + 3 * m;
                    px0 = fmaf(v0p[0], w0[i], px0);
                    py0 = fmaf(v0p[1], w0[i], py0);
                    pz0 = fmaf(v0p[2], w0[i], pz0);
                    px1 = fmaf(v1p[0], w1[i], px1);
                    py1 = fmaf(v1p[1], w1[i], py1);
                    pz1 = fmaf(v1p[2], w1[i], pz1);
                }
                px0 = bfly4(px0); py0 = bfly4(py0); pz0 = bfly4(pz0);
                px1 = bfly4(px1); py1 = bfly4(py1); pz1 = bfly4(pz1);
                if (qc < 3) {
                    float ps0 = (qc == 0) ? px0 : ((qc == 1) ? py0 : pz0);
                    float ps1 = (qc == 0) ? px1 : ((qc == 1) ? py1 : pz1);
                    int o = 32 + 3 * (g - 80) + qc;
                    msg_lo[o] += KVS[0] * ps0;
                    msg_hi[o] += KVS[1] * ps1;
                }
            } else {                             // vv1: cross(v1,v2) on the fly
                float px0 = 0.f, py0 = 0.f, pz0 = 0.f;
                float px1 = 0.f, py1 = 0.f, pz1 = 0.f;
                #pragma unroll
                for (int i = 0; i < 4; i++) {
                    int m = (i >> 1) * 8 + 2 * qc + (i & 1);
                    const float* v0p = xs0 + 3 * m;
                    float cx = v0p[1] * V2Z[0] - v0p[2] * V2Y[0];
                    float cy = v0p[2] * V2X[0] - v0p[0] * V2Z[0];
                    float cz = v0p[0] * V2Y[0] - v0p[1] * V2X[0];
                    px0 = fmaf(cx, w0[i], px0);
                    py0 = fmaf(cy, w0[i], py0);
                    pz0 = fmaf(cz, w0[i], pz0);
                    const float* v1p = xs1 + 3 * m;
                    float dx = v1p[1] * V2Z[1] - v1p[2] * V2Y[1];
                    float dy = v1p[2] * V2X[1] - v1p[0] * V2Z[1];
                    float dz = v1p[0] * V2Y[1] - v1p[1] * V2X[1];
                    px1 = fmaf(dx, w1[i], px1);
                    py1 = fmaf(dy, w1[i], py1);
                    pz1 = fmaf(dz, w1[i], pz1);
                }
                px0 = bfly4(px0); py0 = bfly4(py0); pz0 = bfly4(pz0);
                px1 = bfly4(px1); py1 = bfly4(py1); pz1 = bfly4(pz1);
                if (qc < 3) {
                    float ps0 = (qc == 0) ? px0 : ((qc == 1) ? py0 : pz0);
                    float ps1 = (qc == 0) ? px1 : ((qc == 1) ? py1 : pz1);
                    int o = 32 + 3 * (g - 96) + qc;
                    msg_lo[o] += C_A1I2 * ps0;
                    msg_hi[o] += C_A1I2 * ps1;
                }
            }
        }
    }
    __syncthreads();

    // ---- final scatter: g_acc is [j][n] ----
    for (int idx = tid; idx < 128 * 80; idx += NTHREADS) {
        int e = idx / 80;
        int j = idx - e * 80;
        if (e0 + e < E)
            atomicAdd(&g_acc[j * NNODES + dst_s[e]], msg_s[e * 81 + j]);
    }
}

// ---------------- finalize: 64 nodes/block, 4 roles/node ----------------
__global__ __launch_bounds__(256)
void finalize_kernel(const float* __restrict__ x_dst,
                     const float* __restrict__ Wr0,
                     const float* __restrict__ Wr1,
                     float* __restrict__ out, int N)
{
    __shared__ float msg_s[80 * 64];
    __shared__ float gate_s[64 * 17];
    __shared__ float cnt_s[64];
    __shared__ float Wr0_s[512];
    __shared__ float Wr1_s[256];

    const int tid  = threadIdx.x;
    const int n0   = blockIdx.x * 64;
    const int role = tid >> 6;        // 0: scalars, 1: gates, 2: vec o0-7, 3: vec o8-15
    const int nl   = tid & 63;
    const int n    = n0 + nl;
    const bool valid = (n < N);

    for (int idx = tid; idx < 1280; idx += 256) {
        int j = idx >> 4, t4 = (idx & 15) * 4;
        int nn = n0 + t4;
        float4 v = make_float4(0.f, 0.f, 0.f, 0.f);
        if (nn + 3 < N) {
            v = *(const float4*)&g_acc[j * NNODES + nn];
        } else {
            if (nn + 0 < N) v.x = g_acc[j * NNODES + nn + 0];
            if (nn + 1 < N) v.y = g_acc[j * NNODES + nn + 1];
            if (nn + 2 < N) v.z = g_acc[j * NNODES + nn + 2];
            if (nn + 3 < N) v.w = g_acc[j * NNODES + nn + 3];
        }
        *(float4*)&msg_s[j * 64 + t4] = v;
    }
    if (tid < 64) {
        int nn = n0 + tid;
        cnt_s[tid] = (nn < N) ? g_cnt[nn] : 1.f;
    }
    for (int idx = tid; idx < 512; idx += 256) Wr0_s[idx] = Wr0[idx];
    if (tid < 256) Wr1_s[tid] = Wr1[tid];
    __syncthreads();

    const float inv = 1.f / fmaxf(cnt_s[nl], 1.f);
    const float* xd = x_dst + (size_t)n * 64;
    float* op = out + (size_t)n * 64;

    float vtx[8], vty[8], vtz[8];

    if (role == 0) {
        if (valid) {
            float sd[16];
            #pragma unroll
            for (int i = 0; i < 4; i++) {
                float4 v = __ldg((const float4*)(xd + 4 * i));
                sd[4*i] = v.x; sd[4*i+1] = v.y; sd[4*i+2] = v.z; sd[4*i+3] = v.w;
            }
            #pragma unroll 4
            for (int o = 0; o < 16; o++) {
                float t = 0.f;
                #pragma unroll
                for (int m = 0; m < 16; m++) t = fmaf(sd[m], Wr0_s[m * 32 + o], t);
                op[o] = fmaxf(msg_s[o * 64 + nl] * inv + 0.25f * t, 0.f);
            }
        }
    } else if (role == 1) {
        if (valid) {
            float sd[16];
            #pragma unroll
            for (int i = 0; i < 4; i++) {
                float4 v = __ldg((const float4*)(xd + 4 * i));
                sd[4*i] = v.x; sd[4*i+1] = v.y; sd[4*i+2] = v.z; sd[4*i+3] = v.w;
            }
            #pragma unroll 4
            for (int o = 0; o < 16; o++) {
                float t = 0.f;
                #pragma unroll
                for (int m = 0; m < 16; m++) t = fmaf(sd[m], Wr0_s[m * 32 + 16 + o], t);
                float v = msg_s[(16 + o) * 64 + nl] * inv + 0.25f * t;
                gate_s[nl * 17 + o] = 1.f / (1.f + expf(-v));
            }
        }
    } else {
        if (valid) {
            float vd[48];
            #pragma unroll
            for (int i = 0; i < 12; i++) {
                float4 v = __ldg((const float4*)(xd + 16 + 4 * i));
                vd[4*i] = v.x; vd[4*i+1] = v.y; vd[4*i+2] = v.z; vd[4*i+3] = v.w;
            }
            const int ob = (role - 2) * 8;
            #pragma unroll
            for (int oo = 0; oo < 8; oo++) {
                int o = ob + oo;
                float tx = 0.f, ty = 0.f, tz = 0.f;
                #pragma unroll
                for (int m = 0; m < 16; m++) {
                    float w = Wr1_s[m * 16 + o];
                    tx = fmaf(vd[3*m+0], w, tx);
                    ty = fmaf(vd[3*m+1], w, ty);
                    tz = fmaf(vd[3*m+2], w, tz);
                }
                vtx[oo] = tx; vty[oo] = ty; vtz[oo] = tz;
            }
        }
    }
    __syncthreads();

    if (role >= 2 && valid) {
        const int ob = (role - 2) * 8;
        #pragma unroll
        for (int oo = 0; oo < 8; oo++) {
            int o = ob + oo;
            float g = gate_s[nl * 17 + o];
            int jb = 32 + 3 * o;
            op[16 + 3*o + 0] = (msg_s[(jb + 0) * 64 + nl] * inv + 0.25f * vtx[oo]) * g;
            op[16 + 3*o + 1] = (msg_s[(jb + 1) * 64 + nl] * inv + 0.25f * vty[oo]) * g;
            op[16 + 3*o + 2] = (msg_s[(jb + 2) * 64 + nl] * inv + 0.25f * vtz[oo]) * g;
        }
    }
}

// ---------------- launch ----------------
extern "C" void kernel_launch(void* const* d_in, const int* in_sizes, int n_in,
                              void* d_out, int out_size)
{
    const int*   dst       = (const int*)  d_in[0];
    const float* x_src     = (const float*)d_in[1];
    const float* x_dst     = (const float*)d_in[2];
    const float* sh        = (const float*)d_in[3];
    const float* edge_attr = (const float*)d_in[4];
    const float* We1       = (const float*)d_in[5];
    const float* be1       = (const float*)d_in[6];
    const float* We2       = (const float*)d_in[7];
    const float* be2       = (const float*)d_in[8];
    const float* Wr0       = (const float*)d_in[9];
    const float* Wr1       = (const float*)d_in[10];
    float* out = (float*)d_out;

    int E = in_sizes[0];
    int N = in_sizes[2] / 64;

    cudaFuncSetAttribute(conv_main_kernel,
                         cudaFuncAttributeMaxDynamicSharedMemorySize, SMEM_TOT);

    int prep_total = 128 * 1792 + NCHUNK * 32 * 8;
    prep_kernel<<<(prep_total + 255) / 256, 256>>>(We2);
    int nb = (E + TE - 1) / TE;
    conv_main_kernel<<<nb, NTHREADS, SMEM_TOT>>>(dst, x_src, sh, edge_attr,
                                                 We1, be1, be2, E);
    finalize_kernel<<<(N + 63) / 64, 256>>>(x_dst, Wr0, Wr1, out, N);
}